// round 1
// baseline (speedup 1.0000x reference)
#include <cuda_runtime.h>
#include <cstdint>

// Problem constants (fixed shapes)
#define N_TOK 4096
#define H_DIM 2048
#define I_DIM 1408
#define N_EXP 8
#define CAP   1280   // int(1.25 * (2*N/E))

// GEMM tiling
#define BM 128
#define BN 64
#define BK 16
#define KSTR 20      // padded smem row stride (floats), keeps float4 alignment

// ----------------------------- scratch (static device globals) -------------
__device__ int   g_top2idx[2 * N_TOK];
__device__ float g_top2val[2 * N_TOK];
__device__ int   g_tokens[N_EXP * CAP];
__device__ float g_wts[N_EXP * CAP];
__device__ int   g_counts[N_EXP];
__device__ float g_P[(size_t)N_EXP * CAP * I_DIM];   // swiglu intermediate

// ----------------------------- helpers -------------------------------------
__device__ __forceinline__ float tf32r(float x) {
    unsigned u;
    asm("cvt.rna.tf32.f32 %0, %1;" : "=r"(u) : "f"(x));
    return __uint_as_float(u);
}

__device__ __forceinline__ void mma_tf32(float* c, const float* a, const float* b) {
    asm volatile(
        "mma.sync.aligned.m16n8k8.row.col.f32.tf32.tf32.f32 "
        "{%0,%1,%2,%3}, {%4,%5,%6,%7}, {%8,%9}, {%0,%1,%2,%3};"
        : "+f"(c[0]), "+f"(c[1]), "+f"(c[2]), "+f"(c[3])
        : "r"(__float_as_uint(a[0])), "r"(__float_as_uint(a[1])),
          "r"(__float_as_uint(a[2])), "r"(__float_as_uint(a[3])),
          "r"(__float_as_uint(b[0])), "r"(__float_as_uint(b[1])));
}

// ----------------------------- zero output ---------------------------------
__global__ void zero_kernel(float4* out, int n4) {
    int i = blockIdx.x * blockDim.x + threadIdx.x;
    if (i < n4) out[i] = make_float4(0.f, 0.f, 0.f, 0.f);
}

// ----------------------------- router --------------------------------------
// One warp per token: 8 logits, softmax, top-2 (top_k tie semantics).
__global__ void router_kernel(const float* __restrict__ x, const float* __restrict__ Wr) {
    const int warp = threadIdx.x >> 5;
    const int lane = threadIdx.x & 31;
    const int n = blockIdx.x * 8 + warp;

    const float4* xr = reinterpret_cast<const float4*>(x) + (size_t)n * (H_DIM / 4);
    const float4* wr = reinterpret_cast<const float4*>(Wr);

    float acc[N_EXP];
#pragma unroll
    for (int e = 0; e < N_EXP; e++) acc[e] = 0.f;

    for (int i = lane; i < H_DIM / 4; i += 32) {
        float4 xv = xr[i];
#pragma unroll
        for (int e = 0; e < N_EXP; e++) {
            float4 wv = wr[e * (H_DIM / 4) + i];
            acc[e] += xv.x * wv.x + xv.y * wv.y + xv.z * wv.z + xv.w * wv.w;
        }
    }
#pragma unroll
    for (int off = 16; off > 0; off >>= 1) {
#pragma unroll
        for (int e = 0; e < N_EXP; e++)
            acc[e] += __shfl_xor_sync(0xffffffffu, acc[e], off);
    }

    if (lane == 0) {
        float m = acc[0];
#pragma unroll
        for (int e = 1; e < N_EXP; e++) m = fmaxf(m, acc[e]);
        float ex[N_EXP];
        float s = 0.f;
#pragma unroll
        for (int e = 0; e < N_EXP; e++) { ex[e] = __expf(acc[e] - m); s += ex[e]; }
        float inv = 1.f / s;

        float v1 = -1.f; int i1 = 0;
#pragma unroll
        for (int e = 0; e < N_EXP; e++) if (ex[e] > v1) { v1 = ex[e]; i1 = e; }
        float v2 = -1.f; int i2 = 0;
#pragma unroll
        for (int e = 0; e < N_EXP; e++) if (e != i1 && ex[e] > v2) { v2 = ex[e]; i2 = e; }

        g_top2idx[n]         = i1;
        g_top2idx[N_TOK + n] = i2;
        g_top2val[n]         = v1 * inv;
        g_top2val[N_TOK + n] = v2 * inv;
    }
}

// ----------------------------- capacity scheduler ---------------------------
// Single block, 1024 threads, 8 items each. Order-exact per-expert prefix
// scan over the 8192 flat assignments (slot0 tokens 0..N-1 then slot1),
// matching the reference cumsum ranking. Counts fit in 16 bits (<=8192),
// so 8 expert counters are packed into 4 uint32 (2 x u16 lanes each).
__global__ void sched_kernel() {
    const int tid  = threadIdx.x;           // 0..1023
    const int lane = tid & 31;
    const int wid  = tid >> 5;

    // default-fill the per-expert lists (padding rows: token 0, weight 0)
    for (int i = tid; i < N_EXP * CAP; i += 1024) {
        g_tokens[i] = 0;
        g_wts[i] = 0.f;
    }

    int   e_loc[8];
    float v_loc[8];
    unsigned pk[4] = {0u, 0u, 0u, 0u};
#pragma unroll
    for (int j = 0; j < 8; j++) {
        int p = tid * 8 + j;
        int e = g_top2idx[p];
        e_loc[j] = e;
        v_loc[j] = g_top2val[p];
        pk[e >> 1] += 1u << ((e & 1) * 16);
    }
    unsigned own[4] = {pk[0], pk[1], pk[2], pk[3]};

    // warp inclusive scan of packed counters
#pragma unroll
    for (int off = 1; off < 32; off <<= 1) {
#pragma unroll
        for (int w = 0; w < 4; w++) {
            unsigned u = __shfl_up_sync(0xffffffffu, pk[w], off);
            if (lane >= off) pk[w] += u;
        }
    }

    __shared__ unsigned wsum[32][4];
    if (lane == 31) {
#pragma unroll
        for (int w = 0; w < 4; w++) wsum[wid][w] = pk[w];
    }
    __syncthreads();
    if (wid == 0) {
        unsigned q[4];
#pragma unroll
        for (int w = 0; w < 4; w++) q[w] = wsum[lane][w];
#pragma unroll
        for (int off = 1; off < 32; off <<= 1) {
#pragma unroll
            for (int w = 0; w < 4; w++) {
                unsigned u = __shfl_up_sync(0xffffffffu, q[w], off);
                if (lane >= off) q[w] += u;
            }
        }
#pragma unroll
        for (int w = 0; w < 4; w++) wsum[lane][w] = q[w];
    }
    __syncthreads();

    int off8[8];
#pragma unroll
    for (int w = 0; w < 4; w++) {
        unsigned ex = pk[w] - own[w] + (wid ? wsum[wid - 1][w] : 0u);
        off8[2 * w]     = (int)(ex & 0xFFFFu);
        off8[2 * w + 1] = (int)(ex >> 16);
    }

#pragma unroll
    for (int j = 0; j < 8; j++) {
        int e = e_loc[j];
        int r = off8[e]++;
        if (r < CAP) {
            g_tokens[e * CAP + r] = (tid * 8 + j) & (N_TOK - 1);
            g_wts[e * CAP + r]    = v_loc[j];
        }
    }

    if (tid == 0) {
#pragma unroll
        for (int e = 0; e < N_EXP; e++) {
            unsigned u = wsum[31][e >> 1];
            unsigned tot = (e & 1) ? (u >> 16) : (u & 0xFFFFu);
            g_counts[e] = (tot > CAP) ? CAP : (int)tot;
        }
    }
}

// ----------------------------- gate+up GEMM + SwiGLU ------------------------
// Per expert: P[m, i] = silu(A@Wg^T) * (A@Wu^T); A rows gathered by token id.
// 128x64x16 tiles, TF32 mma.sync, double-buffered smem + register prefetch.
__global__ __launch_bounds__(256, 2)
void gu_kernel(const float* __restrict__ x,
               const float* __restrict__ Wg, const float* __restrict__ Wu) {
    const int e  = blockIdx.z;
    const int m0 = blockIdx.x * BM;   // m-tile fastest varying -> weight reuse in L2
    const int n0 = blockIdx.y * BN;
    if (m0 >= g_counts[e]) return;

    __shared__ float As[2][BM][KSTR];
    __shared__ float Bg[2][BN][KSTR];
    __shared__ float Bu[2][BN][KSTR];
    __shared__ int   toks[BM];

    const int tid = threadIdx.x;
    if (tid < BM) toks[tid] = g_tokens[e * CAP + m0 + tid];
    __syncthreads();

    const int r0 = tid >> 2;
    const int c4 = (tid & 3) * 4;

    const float* xa0 = x + (size_t)toks[r0]      * H_DIM + c4;
    const float* xa1 = x + (size_t)toks[64 + r0] * H_DIM + c4;
    const float* pg  = Wg + ((size_t)e * I_DIM + n0 + r0) * H_DIM + c4;
    const float* pu  = Wu + ((size_t)e * I_DIM + n0 + r0) * H_DIM + c4;

    const int lane = tid & 31;
    const int wid  = tid >> 5;
    const int wm   = (wid >> 1) * 32;
    const int wn   = (wid & 1) * 32;
    const int g    = lane >> 2;
    const int t4   = lane & 3;

    float accg[2][4][4], accu[2][4][4];
#pragma unroll
    for (int mt = 0; mt < 2; mt++)
#pragma unroll
        for (int nt = 0; nt < 4; nt++)
#pragma unroll
            for (int q = 0; q < 4; q++) { accg[mt][nt][q] = 0.f; accu[mt][nt][q] = 0.f; }

    float4 pa0, pa1, pbg, pbu;

    auto LDG = [&](int kt) {
        int k = kt * BK;
        pa0 = *reinterpret_cast<const float4*>(xa0 + k);
        pa1 = *reinterpret_cast<const float4*>(xa1 + k);
        pbg = *reinterpret_cast<const float4*>(pg + k);
        pbu = *reinterpret_cast<const float4*>(pu + k);
    };
    auto STS = [&](int buf) {
        float* a0 = &As[buf][r0][c4];
        a0[0] = tf32r(pa0.x); a0[1] = tf32r(pa0.y); a0[2] = tf32r(pa0.z); a0[3] = tf32r(pa0.w);
        float* a1 = &As[buf][64 + r0][c4];
        a1[0] = tf32r(pa1.x); a1[1] = tf32r(pa1.y); a1[2] = tf32r(pa1.z); a1[3] = tf32r(pa1.w);
        float* bg = &Bg[buf][r0][c4];
        bg[0] = tf32r(pbg.x); bg[1] = tf32r(pbg.y); bg[2] = tf32r(pbg.z); bg[3] = tf32r(pbg.w);
        float* bu = &Bu[buf][r0][c4];
        bu[0] = tf32r(pbu.x); bu[1] = tf32r(pbu.y); bu[2] = tf32r(pbu.z); bu[3] = tf32r(pbu.w);
    };
    auto COMPUTE = [&](int buf) {
#pragma unroll
        for (int s = 0; s < 2; s++) {
            const int ka = s * 8 + t4;
            float a[2][4];
#pragma unroll
            for (int mt = 0; mt < 2; mt++) {
                int r = wm + mt * 16 + g;
                a[mt][0] = As[buf][r][ka];
                a[mt][1] = As[buf][r + 8][ka];
                a[mt][2] = As[buf][r][ka + 4];
                a[mt][3] = As[buf][r + 8][ka + 4];
            }
            float bg[4][2], bu[4][2];
#pragma unroll
            for (int nt = 0; nt < 4; nt++) {
                int n = wn + nt * 8 + g;
                bg[nt][0] = Bg[buf][n][ka]; bg[nt][1] = Bg[buf][n][ka + 4];
                bu[nt][0] = Bu[buf][n][ka]; bu[nt][1] = Bu[buf][n][ka + 4];
            }
#pragma unroll
            for (int mt = 0; mt < 2; mt++)
#pragma unroll
                for (int nt = 0; nt < 4; nt++) {
                    mma_tf32(accg[mt][nt], a[mt], bg[nt]);
                    mma_tf32(accu[mt][nt], a[mt], bu[nt]);
                }
        }
    };

    const int KT = H_DIM / BK;   // 128
    LDG(0); STS(0);
    __syncthreads();
#pragma unroll 1
    for (int kt = 0; kt < KT; kt++) {
        int buf = kt & 1;
        if (kt + 1 < KT) LDG(kt + 1);
        COMPUTE(buf);
        if (kt + 1 < KT) STS(buf ^ 1);
        __syncthreads();
    }

    // epilogue: swiglu -> P (padding rows are finite garbage, masked later)
    float* Pp = g_P + ((size_t)e * CAP + m0) * I_DIM + n0;
#pragma unroll
    for (int mt = 0; mt < 2; mt++)
#pragma unroll
        for (int nt = 0; nt < 4; nt++) {
            int rb = wm + mt * 16 + g;
            int cb = wn + nt * 8 + t4 * 2;
#pragma unroll
            for (int q = 0; q < 4; q++) {
                int rr = rb + ((q >= 2) ? 8 : 0);
                int cc = cb + (q & 1);
                float gv = accg[mt][nt][q];
                float uv = accu[mt][nt][q];
                float sv = gv / (1.f + __expf(-gv));
                Pp[(size_t)rr * I_DIM + cc] = sv * uv;
            }
        }
}

// ----------------------------- down GEMM + weighted scatter -----------------
__global__ __launch_bounds__(256, 2)
void down_kernel(const float* __restrict__ Wd, float* __restrict__ out) {
    const int e  = blockIdx.z;
    const int m0 = blockIdx.x * BM;
    const int n0 = blockIdx.y * BN;
    const int count = g_counts[e];
    if (m0 >= count) return;

    __shared__ float As[2][BM][KSTR];
    __shared__ float Bs[2][BN][KSTR];
    __shared__ int   toks[BM];
    __shared__ float ws[BM];

    const int tid = threadIdx.x;
    if (tid < BM) {
        toks[tid] = g_tokens[e * CAP + m0 + tid];
        ws[tid]   = g_wts[e * CAP + m0 + tid];
    }
    __syncthreads();

    const int r0 = tid >> 2;
    const int c4 = (tid & 3) * 4;

    const float* pa0 = g_P + ((size_t)e * CAP + m0 + r0)      * I_DIM + c4;
    const float* pa1 = g_P + ((size_t)e * CAP + m0 + 64 + r0) * I_DIM + c4;
    const float* pb  = Wd + ((size_t)e * H_DIM + n0 + r0) * I_DIM + c4;

    const int lane = tid & 31;
    const int wid  = tid >> 5;
    const int wm   = (wid >> 1) * 32;
    const int wn   = (wid & 1) * 32;
    const int g    = lane >> 2;
    const int t4   = lane & 3;

    float acc[2][4][4];
#pragma unroll
    for (int mt = 0; mt < 2; mt++)
#pragma unroll
        for (int nt = 0; nt < 4; nt++)
#pragma unroll
            for (int q = 0; q < 4; q++) acc[mt][nt][q] = 0.f;

    float4 fa0, fa1, fb;
    auto LDG = [&](int kt) {
        int k = kt * BK;
        fa0 = *reinterpret_cast<const float4*>(pa0 + k);
        fa1 = *reinterpret_cast<const float4*>(pa1 + k);
        fb  = *reinterpret_cast<const float4*>(pb + k);
    };
    auto STS = [&](int buf) {
        float* a0 = &As[buf][r0][c4];
        a0[0] = tf32r(fa0.x); a0[1] = tf32r(fa0.y); a0[2] = tf32r(fa0.z); a0[3] = tf32r(fa0.w);
        float* a1 = &As[buf][64 + r0][c4];
        a1[0] = tf32r(fa1.x); a1[1] = tf32r(fa1.y); a1[2] = tf32r(fa1.z); a1[3] = tf32r(fa1.w);
        float* b = &Bs[buf][r0][c4];
        b[0] = tf32r(fb.x); b[1] = tf32r(fb.y); b[2] = tf32r(fb.z); b[3] = tf32r(fb.w);
    };
    auto COMPUTE = [&](int buf) {
#pragma unroll
        for (int s = 0; s < 2; s++) {
            const int ka = s * 8 + t4;
            float a[2][4];
#pragma unroll
            for (int mt = 0; mt < 2; mt++) {
                int r = wm + mt * 16 + g;
                a[mt][0] = As[buf][r][ka];
                a[mt][1] = As[buf][r + 8][ka];
                a[mt][2] = As[buf][r][ka + 4];
                a[mt][3] = As[buf][r + 8][ka + 4];
            }
            float b[4][2];
#pragma unroll
            for (int nt = 0; nt < 4; nt++) {
                int n = wn + nt * 8 + g;
                b[nt][0] = Bs[buf][n][ka]; b[nt][1] = Bs[buf][n][ka + 4];
            }
#pragma unroll
            for (int mt = 0; mt < 2; mt++)
#pragma unroll
                for (int nt = 0; nt < 4; nt++)
                    mma_tf32(acc[mt][nt], a[mt], b[nt]);
        }
    };

    const int KT = I_DIM / BK;   // 88
    LDG(0); STS(0);
    __syncthreads();
#pragma unroll 1
    for (int kt = 0; kt < KT; kt++) {
        int buf = kt & 1;
        if (kt + 1 < KT) LDG(kt + 1);
        COMPUTE(buf);
        if (kt + 1 < KT) STS(buf ^ 1);
        __syncthreads();
    }

    // epilogue: weighted scatter-add into output
#pragma unroll
    for (int mt = 0; mt < 2; mt++)
#pragma unroll
        for (int nt = 0; nt < 4; nt++) {
            int rb = wm + mt * 16 + g;
            int cb = wn + nt * 8 + t4 * 2;
#pragma unroll
            for (int q = 0; q < 4; q++) {
                int rl = rb + ((q >= 2) ? 8 : 0);
                if (m0 + rl < count) {
                    int t = toks[rl];
                    float w = ws[rl];
                    int cc = n0 + cb + (q & 1);
                    atomicAdd(&out[(size_t)t * H_DIM + cc], w * acc[mt][nt][q]);
                }
            }
        }
}

// ----------------------------- launch --------------------------------------
extern "C" void kernel_launch(void* const* d_in, const int* in_sizes, int n_in,
                              void* d_out, int out_size) {
    const float* x  = (const float*)d_in[0];
    const float* Wr = (const float*)d_in[1];
    const float* Wg = (const float*)d_in[2];
    const float* Wu = (const float*)d_in[3];
    const float* Wd = (const float*)d_in[4];
    float* out = (float*)d_out;
    (void)in_sizes; (void)n_in;

    int n4 = out_size / 4;
    zero_kernel<<<(n4 + 255) / 256, 256>>>((float4*)out, n4);

    router_kernel<<<N_TOK / 8, 256>>>(x, Wr);
    sched_kernel<<<1, 1024>>>();

    // m-tile fastest-varying so consecutive blocks reuse weight tiles via L2
    dim3 ggrid(CAP / BM, I_DIM / BN, N_EXP);   // (10, 22, 8)
    gu_kernel<<<ggrid, 256>>>(x, Wg, Wu);

    dim3 dgrid(CAP / BM, H_DIM / BN, N_EXP);   // (10, 32, 8)
    down_kernel<<<dgrid, 256>>>(Wd, out);
}